// round 7
// baseline (speedup 1.0000x reference)
#include <cuda_runtime.h>
#include <cuda_bf16.h>

// Problem constants
#define B 32
#define C 3
#define H 640
#define W 640
#define POOL 8
#define CELL 80              // H/POOL
#define HIDDEN 64
#define FEAT (C*POOL*POOL)   // 192
#define NPARAM 15
#define PLANE (H*W)          // 409600
#define PLANE4 (PLANE/4)     // 102400
#define W4 (W/4)             // 160

#define GROUPS 4
#define IMGS_PER_G (B / GROUPS)          // 8
#define CHUNKS_PER_IMG 200               // PLANE4 / 512

// Scratch (allocation-free rule: __device__ globals)
// partial[cell*4 + q]: per-cell row-quarter partial sums (cell = global 0..6143)
__device__ float g_partial[B * FEAT * 4];
__device__ float g_params[B * 16];

// ---------------------------------------------------------------------------
// Kernel 1 (per group of 8 images): pooling stage A — column sums.
// 96 blocks/image: 24 bands (c,pool_row) x 4 row-quarters; 160 threads/block.
// Thread j sums 20 rows of float4-column j (fully coalesced, 20-deep MLP),
// then block reduces 20 float4-cols -> 1 partial per pool col (8 per block).
// ---------------------------------------------------------------------------
__global__ __launch_bounds__(160) void pool_kernel(const float* __restrict__ x,
                                                   float* __restrict__ partial,
                                                   int b0) {
    const int blk  = blockIdx.x;         // 0 .. 8*96-1
    const int img  = blk / 96;
    const int bq   = blk - img * 96;
    const int band = bq >> 2;            // 0..23 = c*8 + pr
    const int q    = bq & 3;             // row quarter (20 rows)
    const int b    = b0 + img;
    const int c    = band >> 3;
    const int pr   = band & 7;

    const float4* p = (const float4*)x
        + ((size_t)(b * C + c) * H + (size_t)(pr * CELL + q * 20)) * W4
        + threadIdx.x;

    float4 a0 = make_float4(0.f, 0.f, 0.f, 0.f);
    float4 a1 = make_float4(0.f, 0.f, 0.f, 0.f);
    #pragma unroll
    for (int r = 0; r < 20; r += 2) {
        float4 v0 = p[(size_t)r * W4];
        float4 v1 = p[(size_t)(r + 1) * W4];
        a0.x += v0.x; a0.y += v0.y; a0.z += v0.z; a0.w += v0.w;
        a1.x += v1.x; a1.y += v1.y; a1.z += v1.z; a1.w += v1.w;
    }
    float s = (a0.x + a0.y + a0.z + a0.w) + (a1.x + a1.y + a1.z + a1.w);

    __shared__ float sm[160];
    sm[threadIdx.x] = s;
    __syncthreads();

    if (threadIdx.x < POOL) {            // 8 pool cols, 20 float4-cols each
        float t = 0.f;
        #pragma unroll
        for (int j = 0; j < 20; ++j) t += sm[threadIdx.x * 20 + j];
        int cell = (b * C + c) * (POOL * POOL) + pr * POOL + threadIdx.x;
        partial[cell * 4 + q] = t;
    }
}

// ---------------------------------------------------------------------------
// Kernel 2 (per group): per-sample MLP; feat[k] = sum of 4 quarter-partials.
// ---------------------------------------------------------------------------
__global__ __launch_bounds__(64) void mlp_kernel(const float* __restrict__ partial,
                                                 const float* __restrict__ W1,
                                                 const float* __restrict__ b1,
                                                 const float* __restrict__ W2,
                                                 float* __restrict__ params,
                                                 int b0) {
    int b = b0 + blockIdx.x;
    int j = threadIdx.x;
    __shared__ float fs[FEAT];
    __shared__ float hs[HIDDEN];

    for (int k = j; k < FEAT; k += HIDDEN) {
        const float* pp = partial + (size_t)(b * FEAT + k) * 4;
        fs[k] = (pp[0] + pp[1] + pp[2] + pp[3]) * (1.f / (CELL * CELL));
    }
    __syncthreads();

    float acc = b1[j];
    #pragma unroll 8
    for (int k = 0; k < FEAT; ++k) acc = fmaf(fs[k], W1[k * HIDDEN + j], acc);
    hs[j] = fminf(fmaxf(acc, 0.f), 6.f);
    __syncthreads();

    if (j < NPARAM) {
        float a = 0.f;
        #pragma unroll 8
        for (int k = 0; k < HIDDEN; ++k) a = fmaf(hs[k], W2[k * NPARAM + j], a);
        params[b * 16 + j] = 1.f / (1.f + __expf(-a));
    }
}

// ---------------------------------------------------------------------------
// Kernel 3 (per group): 3x3 color transform + gamma pow + normalize.
// x reads use DEFAULT caching (we WANT the pool-warmed L2 lines);
// output stores use __stcs (evict-first) so the write stream doesn't
// evict the group's x from L2. 2 float4-groups per thread for ILP.
// ---------------------------------------------------------------------------
__global__ __launch_bounds__(256) void transform_kernel(const float* __restrict__ x,
                                                        const float* __restrict__ params,
                                                        float* __restrict__ out,
                                                        int b0) {
    const int b   = b0 + blockIdx.x / CHUNKS_PER_IMG;
    const int blk = blockIdx.x % CHUNKS_PER_IMG;

    __shared__ float p[16];
    if (threadIdx.x < 16) p[threadIdx.x] = params[b * 16 + threadIdx.x];
    __syncthreads();

    const float m00 = p[0], m01 = p[1], m02 = p[2];
    const float m10 = p[3], m11 = p[4], m12 = p[5];
    const float m20 = p[6], m21 = p[7], m22 = p[8];
    const float bi0 = p[9], bi1 = p[10], bi2 = p[11];
    const float g0  = p[12], g1 = p[13], g2 = p[14];

    const float s0 = 1.0f / 0.229f, s1 = 1.0f / 0.224f, s2 = 1.0f / 0.225f;
    const float t0 = -0.485f / 0.229f, t1 = -0.456f / 0.224f, t2 = -0.406f / 0.225f;

    const int i4a = blk * 512 + threadIdx.x;
    const int i4b = i4a + 256;
    const float4* xb = (const float4*)(x + (size_t)b * C * PLANE);
    float4* ob = (float4*)(out + (size_t)b * C * PLANE);

    float4 xa0 = xb[i4a];
    float4 xc0 = xb[i4a + PLANE4];
    float4 xd0 = xb[i4a + 2 * PLANE4];
    float4 xa1 = xb[i4b];
    float4 xc1 = xb[i4b + PLANE4];
    float4 xd1 = xb[i4b + 2 * PLANE4];

    float4 o00, o10, o20, o01, o11, o21;
    #define DO_ELEM(XA, XC, XD, O0, O1, O2, FLD)                                   \
    {                                                                              \
        float a = XA.FLD, bch = XC.FLD, cch = XD.FLD;                              \
        float y0 = fmaf(m00, a, fmaf(m01, bch, fmaf(m02, cch, bi0)));              \
        float y1 = fmaf(m10, a, fmaf(m11, bch, fmaf(m12, cch, bi1)));              \
        float y2 = fmaf(m20, a, fmaf(m21, bch, fmaf(m22, cch, bi2)));              \
        y0 = fmaxf(y0, 1e-20f); y1 = fmaxf(y1, 1e-20f); y2 = fmaxf(y2, 1e-20f);    \
        O0.FLD = fmaf(__powf(y0, g0), s0, t0);                                     \
        O1.FLD = fmaf(__powf(y1, g1), s1, t1);                                     \
        O2.FLD = fmaf(__powf(y2, g2), s2, t2);                                     \
    }
    DO_ELEM(xa0, xc0, xd0, o00, o10, o20, x)
    DO_ELEM(xa1, xc1, xd1, o01, o11, o21, x)
    DO_ELEM(xa0, xc0, xd0, o00, o10, o20, y)
    DO_ELEM(xa1, xc1, xd1, o01, o11, o21, y)
    DO_ELEM(xa0, xc0, xd0, o00, o10, o20, z)
    DO_ELEM(xa1, xc1, xd1, o01, o11, o21, z)
    DO_ELEM(xa0, xc0, xd0, o00, o10, o20, w)
    DO_ELEM(xa1, xc1, xd1, o01, o11, o21, w)
    #undef DO_ELEM

    __stcs(ob + i4a,              o00);
    __stcs(ob + i4a + PLANE4,     o10);
    __stcs(ob + i4a + 2 * PLANE4, o20);
    __stcs(ob + i4b,              o01);
    __stcs(ob + i4b + PLANE4,     o11);
    __stcs(ob + i4b + 2 * PLANE4, o21);
}

// ---------------------------------------------------------------------------
extern "C" void kernel_launch(void* const* d_in, const int* in_sizes, int n_in,
                              void* d_out, int out_size) {
    const float* x  = (const float*)d_in[0];   // (32,3,640,640)
    const float* W1 = (const float*)d_in[1];   // (192,64)
    const float* b1 = (const float*)d_in[2];   // (64,)
    const float* W2 = (const float*)d_in[3];   // (64,15)
    float* out = (float*)d_out;

    float* partial; cudaGetSymbolAddress((void**)&partial, g_partial);
    float* params;  cudaGetSymbolAddress((void**)&params,  g_params);

    for (int g = 0; g < GROUPS; ++g) {
        int b0 = g * IMGS_PER_G;
        pool_kernel<<<IMGS_PER_G * 96, 160>>>(x, partial, b0);
        mlp_kernel<<<IMGS_PER_G, HIDDEN>>>(partial, W1, b1, W2, params, b0);
        transform_kernel<<<IMGS_PER_G * CHUNKS_PER_IMG, 256>>>(x, params, out, b0);
    }
}

// round 8
// speedup vs baseline: 1.6052x; 1.6052x over previous
#include <cuda_runtime.h>
#include <cuda_bf16.h>

// Problem constants
#define B 32
#define C 3
#define H 640
#define W 640
#define POOL 8
#define CELL 80              // H/POOL
#define HIDDEN 64
#define FEAT (C*POOL*POOL)   // 192
#define NPARAM 15
#define PLANE (H*W)          // 409600
#define PLANE4 (PLANE/4)     // 102400
#define W4 (W/4)             // 160

#define CHUNKS_PER_IMG 200               // PLANE4 / 512
#define POOL_BLOCKS (B * C * POOL * 4)   // 3072: (b,c,pr) bands x 4 row-quarters

// Scratch (allocation-free rule: __device__ globals)
// partial[cell*4 + q]: per-cell row-quarter partial sums (cell = 0..6143)
__device__ float g_partial[B * FEAT * 4];
__device__ float g_params[B * 16];

// ---------------------------------------------------------------------------
// Kernel 1 (FULL BATCH): pooling stage A — column sums.
// 3072 blocks = 32 imgs x 24 bands (c,pool_row) x 4 row-quarters.
// 160 threads/block: thread j sums 20 rows of float4-column j
// (fully coalesced, pure float4, zero per-iteration ALU), then block
// reduces 20 float4-cols -> 1 partial per pool col (8 per block).
// ---------------------------------------------------------------------------
__global__ __launch_bounds__(160) void pool_kernel(const float* __restrict__ x,
                                                   float* __restrict__ partial) {
    const int blk  = blockIdx.x;         // 0 .. 3071
    const int b    = blk / 96;
    const int bq   = blk - b * 96;
    const int band = bq >> 2;            // 0..23 = c*8 + pr
    const int q    = bq & 3;             // row quarter (20 rows)
    const int c    = band >> 3;
    const int pr   = band & 7;

    const float4* p = (const float4*)x
        + ((size_t)(b * C + c) * H + (size_t)(pr * CELL + q * 20)) * W4
        + threadIdx.x;

    float4 a0 = make_float4(0.f, 0.f, 0.f, 0.f);
    float4 a1 = make_float4(0.f, 0.f, 0.f, 0.f);
    #pragma unroll
    for (int r = 0; r < 20; r += 2) {
        float4 v0 = p[(size_t)r * W4];
        float4 v1 = p[(size_t)(r + 1) * W4];
        a0.x += v0.x; a0.y += v0.y; a0.z += v0.z; a0.w += v0.w;
        a1.x += v1.x; a1.y += v1.y; a1.z += v1.z; a1.w += v1.w;
    }
    float s = (a0.x + a0.y + a0.z + a0.w) + (a1.x + a1.y + a1.z + a1.w);

    __shared__ float sm[160];
    sm[threadIdx.x] = s;
    __syncthreads();

    if (threadIdx.x < POOL) {            // 8 pool cols, 20 float4-cols each
        float t = 0.f;
        #pragma unroll
        for (int j = 0; j < 20; ++j) t += sm[threadIdx.x * 20 + j];
        int cell = (b * C + c) * (POOL * POOL) + pr * POOL + threadIdx.x;
        partial[cell * 4 + q] = t;
    }
}

// ---------------------------------------------------------------------------
// Kernel 2: per-sample MLP; feat[k] = sum of 4 quarter-partials.
// ---------------------------------------------------------------------------
__global__ __launch_bounds__(64) void mlp_kernel(const float* __restrict__ partial,
                                                 const float* __restrict__ W1,
                                                 const float* __restrict__ b1,
                                                 const float* __restrict__ W2,
                                                 float* __restrict__ params) {
    int b = blockIdx.x;
    int j = threadIdx.x;
    __shared__ float fs[FEAT];
    __shared__ float hs[HIDDEN];

    for (int k = j; k < FEAT; k += HIDDEN) {
        const float* pp = partial + (size_t)(b * FEAT + k) * 4;
        fs[k] = (pp[0] + pp[1] + pp[2] + pp[3]) * (1.f / (CELL * CELL));
    }
    __syncthreads();

    float acc = b1[j];
    #pragma unroll 8
    for (int k = 0; k < FEAT; ++k) acc = fmaf(fs[k], W1[k * HIDDEN + j], acc);
    hs[j] = fminf(fmaxf(acc, 0.f), 6.f);
    __syncthreads();

    if (j < NPARAM) {
        float a = 0.f;
        #pragma unroll 8
        for (int k = 0; k < HIDDEN; ++k) a = fmaf(hs[k], W2[k * NPARAM + j], a);
        params[b * 16 + j] = 1.f / (1.f + __expf(-a));
    }
}

// ---------------------------------------------------------------------------
// Kernel 3: IDENTICAL to the round-6 96.5us version.
// 2 float4-groups per thread (ILP), __ldcs reads, __stcs evict-first
// stores, reverse block order.
// ---------------------------------------------------------------------------
__global__ __launch_bounds__(256) void transform_kernel(const float* __restrict__ x,
                                                        const float* __restrict__ params,
                                                        float* __restrict__ out) {
    const int rev = (B * CHUNKS_PER_IMG - 1) - blockIdx.x;  // reversed order
    const int b   = rev / CHUNKS_PER_IMG;
    const int blk = rev - b * CHUNKS_PER_IMG;

    __shared__ float p[16];
    if (threadIdx.x < 16) p[threadIdx.x] = params[b * 16 + threadIdx.x];
    __syncthreads();

    const float m00 = p[0], m01 = p[1], m02 = p[2];
    const float m10 = p[3], m11 = p[4], m12 = p[5];
    const float m20 = p[6], m21 = p[7], m22 = p[8];
    const float bi0 = p[9], bi1 = p[10], bi2 = p[11];
    const float g0  = p[12], g1 = p[13], g2 = p[14];

    const float s0 = 1.0f / 0.229f, s1 = 1.0f / 0.224f, s2 = 1.0f / 0.225f;
    const float t0 = -0.485f / 0.229f, t1 = -0.456f / 0.224f, t2 = -0.406f / 0.225f;

    const int i4a = blk * 512 + threadIdx.x;
    const int i4b = i4a + 256;
    const float4* xb = (const float4*)(x + (size_t)b * C * PLANE);
    float4* ob = (float4*)(out + (size_t)b * C * PLANE);

    float4 xa0 = __ldcs(xb + i4a);
    float4 xc0 = __ldcs(xb + i4a + PLANE4);
    float4 xd0 = __ldcs(xb + i4a + 2 * PLANE4);
    float4 xa1 = __ldcs(xb + i4b);
    float4 xc1 = __ldcs(xb + i4b + PLANE4);
    float4 xd1 = __ldcs(xb + i4b + 2 * PLANE4);

    float4 o00, o10, o20, o01, o11, o21;
    #define DO_ELEM(XA, XC, XD, O0, O1, O2, FLD)                                   \
    {                                                                              \
        float a = XA.FLD, bch = XC.FLD, cch = XD.FLD;                              \
        float y0 = fmaf(m00, a, fmaf(m01, bch, fmaf(m02, cch, bi0)));              \
        float y1 = fmaf(m10, a, fmaf(m11, bch, fmaf(m12, cch, bi1)));              \
        float y2 = fmaf(m20, a, fmaf(m21, bch, fmaf(m22, cch, bi2)));              \
        y0 = fmaxf(y0, 1e-20f); y1 = fmaxf(y1, 1e-20f); y2 = fmaxf(y2, 1e-20f);    \
        O0.FLD = fmaf(__powf(y0, g0), s0, t0);                                     \
        O1.FLD = fmaf(__powf(y1, g1), s1, t1);                                     \
        O2.FLD = fmaf(__powf(y2, g2), s2, t2);                                     \
    }
    DO_ELEM(xa0, xc0, xd0, o00, o10, o20, x)
    DO_ELEM(xa1, xc1, xd1, o01, o11, o21, x)
    DO_ELEM(xa0, xc0, xd0, o00, o10, o20, y)
    DO_ELEM(xa1, xc1, xd1, o01, o11, o21, y)
    DO_ELEM(xa0, xc0, xd0, o00, o10, o20, z)
    DO_ELEM(xa1, xc1, xd1, o01, o11, o21, z)
    DO_ELEM(xa0, xc0, xd0, o00, o10, o20, w)
    DO_ELEM(xa1, xc1, xd1, o01, o11, o21, w)
    #undef DO_ELEM

    __stcs(ob + i4a,              o00);
    __stcs(ob + i4a + PLANE4,     o10);
    __stcs(ob + i4a + 2 * PLANE4, o20);
    __stcs(ob + i4b,              o01);
    __stcs(ob + i4b + PLANE4,     o11);
    __stcs(ob + i4b + 2 * PLANE4, o21);
}

// ---------------------------------------------------------------------------
extern "C" void kernel_launch(void* const* d_in, const int* in_sizes, int n_in,
                              void* d_out, int out_size) {
    const float* x  = (const float*)d_in[0];   // (32,3,640,640)
    const float* W1 = (const float*)d_in[1];   // (192,64)
    const float* b1 = (const float*)d_in[2];   // (64,)
    const float* W2 = (const float*)d_in[3];   // (64,15)
    float* out = (float*)d_out;

    float* partial; cudaGetSymbolAddress((void**)&partial, g_partial);
    float* params;  cudaGetSymbolAddress((void**)&params,  g_params);

    pool_kernel<<<POOL_BLOCKS, 160>>>(x, partial);            // 3072 blocks
    mlp_kernel<<<B, HIDDEN>>>(partial, W1, b1, W2, params);
    transform_kernel<<<B * CHUNKS_PER_IMG, 256>>>(x, params, out);
}